// round 3
// baseline (speedup 1.0000x reference)
#include <cuda_runtime.h>
#include <math.h>

// Problem constants
// BS=128, NE=512, NQ=128, IN_DIM=512, EMBED=512, OUT=512, H=8, HD=64
// Masks arrive as int32 (bool -> int32 in the harness dtype set).

// Scratch (no cudaMalloc allowed)
__device__ float g_q[8388608];       // (128*128) x 512
__device__ float g_kv[67108864];     // (128*512) x 1024   (cols [0,512)=K, [512,1024)=V)
__device__ float g_attn[8388608];    // (128*128) x 512

// ---------------------------------------------------------------------------
// SGEMM (NT): C[m,n] = sum_k A[m,k] * B[n,k]   (A: MxK row-major, B: NxK row-major)
// 128x128 block tile, BK=8, 256 threads, 8x8 register tile per thread.
// Optional A-row remap (gather first 128 rows of each batch of 512),
// optional bias (per column) and int32 row-mask (zero the row) epilogue.
// ---------------------------------------------------------------------------
__global__ void __launch_bounds__(256) sgemm_nt(
    const float* __restrict__ A, const float* __restrict__ B, float* __restrict__ C,
    int M, int N, int K, int remap_rows, long long remap_stride,
    const float* __restrict__ bias, const int* __restrict__ rmask)
{
    __shared__ float As[8][128];
    __shared__ float Bs[8][128];

    const int tid = threadIdx.x;
    const int m0 = blockIdx.y * 128;
    const int n0 = blockIdx.x * 128;

    const int lr = tid >> 1;          // 0..127
    const int lc = (tid & 1) * 4;     // 0 or 4

    const long long arow = m0 + lr;
    const float* Aptr;
    if (remap_rows)
        Aptr = A + (arow / remap_rows) * remap_stride + (arow % remap_rows) * (long long)K + lc;
    else
        Aptr = A + arow * (long long)K + lc;
    const float* Bptr = B + (long long)(n0 + lr) * K + lc;

    const int tx = tid & 15;          // 0..15 -> n
    const int ty = tid >> 4;          // 0..15 -> m

    float acc[8][8];
    #pragma unroll
    for (int i = 0; i < 8; i++)
        #pragma unroll
        for (int j = 0; j < 8; j++) acc[i][j] = 0.f;

    for (int k0 = 0; k0 < K; k0 += 8) {
        float4 a4 = *(const float4*)Aptr; Aptr += 8;
        float4 b4 = *(const float4*)Bptr; Bptr += 8;
        As[lc + 0][lr] = a4.x; As[lc + 1][lr] = a4.y;
        As[lc + 2][lr] = a4.z; As[lc + 3][lr] = a4.w;
        Bs[lc + 0][lr] = b4.x; Bs[lc + 1][lr] = b4.y;
        Bs[lc + 2][lr] = b4.z; Bs[lc + 3][lr] = b4.w;
        __syncthreads();

        #pragma unroll
        for (int kk = 0; kk < 8; kk++) {
            float a[8], b[8];
            *(float4*)&a[0] = *(const float4*)&As[kk][ty * 8];
            *(float4*)&a[4] = *(const float4*)&As[kk][ty * 8 + 4];
            *(float4*)&b[0] = *(const float4*)&Bs[kk][tx * 8];
            *(float4*)&b[4] = *(const float4*)&Bs[kk][tx * 8 + 4];
            #pragma unroll
            for (int i = 0; i < 8; i++)
                #pragma unroll
                for (int j = 0; j < 8; j++)
                    acc[i][j] += a[i] * b[j];
        }
        __syncthreads();
    }

    // epilogue
    float bv[8];
    if (bias) {
        *(float4*)&bv[0] = *(const float4*)(bias + n0 + tx * 8);
        *(float4*)&bv[4] = *(const float4*)(bias + n0 + tx * 8 + 4);
    } else {
        #pragma unroll
        for (int j = 0; j < 8; j++) bv[j] = 0.f;
    }

    #pragma unroll
    for (int i = 0; i < 8; i++) {
        const int m = m0 + ty * 8 + i;
        const bool zero_row = (rmask != nullptr) && (rmask[m] != 0);
        float4 o0, o1;
        if (zero_row) {
            o0 = make_float4(0.f, 0.f, 0.f, 0.f);
            o1 = make_float4(0.f, 0.f, 0.f, 0.f);
        } else {
            o0 = make_float4(acc[i][0] + bv[0], acc[i][1] + bv[1],
                             acc[i][2] + bv[2], acc[i][3] + bv[3]);
            o1 = make_float4(acc[i][4] + bv[4], acc[i][5] + bv[5],
                             acc[i][6] + bv[6], acc[i][7] + bv[7]);
        }
        float* crow = C + (long long)m * N + n0 + tx * 8;
        *(float4*)crow = o0;
        *(float4*)(crow + 4) = o1;
    }
}

// ---------------------------------------------------------------------------
// Fused attention: per block = (q-chunk of 32, head, batch).
// logits (32x512 in smem) -> masked softmax + diff-mask renorm -> P@V.
// smem: q[32][68] + kT/v[64][68] + w[32][512]  = 91648 B (dynamic)
// ---------------------------------------------------------------------------
#define ATTN_SMEM_BYTES ((32 * 68 + 64 * 68 + 32 * 512) * 4)

__global__ void __launch_bounds__(256) attn_kernel(
    const float* __restrict__ Q, const float* __restrict__ KV,
    const int* __restrict__ pre_mask,
    const float* __restrict__ diff_mask,
    float* __restrict__ Attn)
{
    extern __shared__ float sm[];
    float* q_s  = sm;                        // [32][68]
    float* kv_s = sm + 32 * 68;              // [64][68]
    float* w_s  = sm + 32 * 68 + 64 * 68;    // [32][512]

    const int tid = threadIdx.x;
    const int q0 = blockIdx.x * 32;
    const int h  = blockIdx.y;
    const int b  = blockIdx.z;

    const float* qptr  = Q + ((long long)(b * 128 + q0)) * 512 + h * 64;
    const float* kbase = KV + (long long)b * 512 * 1024 + h * 64;
    const float* vbase = kbase + 512;

    // ---- load Q chunk (32 x 64) ----
    #pragma unroll
    for (int i = 0; i < 2; i++) {
        const int lin = tid + i * 256;
        const int r = lin >> 4, c = (lin & 15) * 4;
        *(float4*)&q_s[r * 68 + c] = *(const float4*)(qptr + (long long)r * 512 + c);
    }

    const int tk = tid & 15;   // key-group / dim-group
    const int tq = tid >> 4;   // q-row group (2 rows each)

    // ---- phase 1: logits = (Q K^T) * 0.125, pre-masked to -inf ----
    for (int kt = 0; kt < 8; kt++) {
        __syncthreads();
        // load K tile transposed: kv_s[d][key]
        #pragma unroll
        for (int i = 0; i < 4; i++) {
            const int lin = tid + i * 256;
            const int key = lin >> 4, c = (lin & 15) * 4;
            float4 v = *(const float4*)(kbase + (long long)(kt * 64 + key) * 1024 + c);
            kv_s[(c + 0) * 68 + key] = v.x;
            kv_s[(c + 1) * 68 + key] = v.y;
            kv_s[(c + 2) * 68 + key] = v.z;
            kv_s[(c + 3) * 68 + key] = v.w;
        }
        __syncthreads();

        float4 l0 = make_float4(0.f, 0.f, 0.f, 0.f);
        float4 l1 = make_float4(0.f, 0.f, 0.f, 0.f);
        const float* qr0 = &q_s[(tq * 2 + 0) * 68];
        const float* qr1 = &q_s[(tq * 2 + 1) * 68];
        #pragma unroll 8
        for (int d = 0; d < 64; d++) {
            float4 k4 = *(const float4*)&kv_s[d * 68 + tk * 4];
            const float qa = qr0[d], qb = qr1[d];
            l0.x += qa * k4.x; l0.y += qa * k4.y; l0.z += qa * k4.z; l0.w += qa * k4.w;
            l1.x += qb * k4.x; l1.y += qb * k4.y; l1.z += qb * k4.z; l1.w += qb * k4.w;
        }

        #pragma unroll
        for (int r = 0; r < 2; r++) {
            const int qi = tq * 2 + r;
            const float4 lv = r ? l1 : l0;
            const int4 m4 = *(const int4*)(pre_mask +
                ((long long)(b * 128 + q0 + qi)) * 512 + kt * 64 + tk * 4);
            float4 o;
            o.x = m4.x ? -INFINITY : lv.x * 0.125f;
            o.y = m4.y ? -INFINITY : lv.y * 0.125f;
            o.z = m4.z ? -INFINITY : lv.z * 0.125f;
            o.w = m4.w ? -INFINITY : lv.w * 0.125f;
            *(float4*)&w_s[qi * 512 + kt * 64 + tk * 4] = o;
        }
    }
    __syncthreads();

    // ---- phase 2: masked softmax + diff-mask renorm (warp per 4 rows) ----
    const int warp = tid >> 5, lane = tid & 31;
    for (int rr = 0; rr < 4; rr++) {
        const int r = warp * 4 + rr;
        float vals[16];
        float mx = -INFINITY;
        #pragma unroll
        for (int i = 0; i < 16; i++) {
            vals[i] = w_s[r * 512 + lane + 32 * i];
            mx = fmaxf(mx, vals[i]);
        }
        #pragma unroll
        for (int o = 16; o > 0; o >>= 1) mx = fmaxf(mx, __shfl_xor_sync(0xffffffffu, mx, o));

        if (mx == -INFINITY) {  // fully masked row -> zeros
            #pragma unroll
            for (int i = 0; i < 16; i++) w_s[r * 512 + lane + 32 * i] = 0.f;
            continue;
        }
        float s1 = 0.f;
        #pragma unroll
        for (int i = 0; i < 16; i++) { vals[i] = __expf(vals[i] - mx); s1 += vals[i]; }
        #pragma unroll
        for (int o = 16; o > 0; o >>= 1) s1 += __shfl_xor_sync(0xffffffffu, s1, o);

        const float* drow = diff_mask + ((long long)(b * 128 + q0 + r)) * 512;
        float s2 = 0.f;
        #pragma unroll
        for (int i = 0; i < 16; i++) { vals[i] *= drow[lane + 32 * i]; s2 += vals[i]; }
        #pragma unroll
        for (int o = 16; o > 0; o >>= 1) s2 += __shfl_xor_sync(0xffffffffu, s2, o);

        // final weight = e*diff / (sum(e*diff) + 1e-8*sum(e))  == reference chain
        const float inv = 1.f / (s2 + 1e-8f * s1);
        #pragma unroll
        for (int i = 0; i < 16; i++) w_s[r * 512 + lane + 32 * i] = vals[i] * inv;
    }

    // ---- phase 3: attn = W @ V ----
    float4 a0 = make_float4(0.f, 0.f, 0.f, 0.f);
    float4 a1 = make_float4(0.f, 0.f, 0.f, 0.f);
    for (int vt = 0; vt < 8; vt++) {
        __syncthreads();
        #pragma unroll
        for (int i = 0; i < 4; i++) {
            const int lin = tid + i * 256;
            const int key = lin >> 4, c = (lin & 15) * 4;
            *(float4*)&kv_s[key * 68 + c] =
                *(const float4*)(vbase + (long long)(vt * 64 + key) * 1024 + c);
        }
        __syncthreads();

        const float* wr0 = &w_s[(tq * 2 + 0) * 512 + vt * 64];
        const float* wr1 = &w_s[(tq * 2 + 1) * 512 + vt * 64];
        #pragma unroll 8
        for (int kk = 0; kk < 64; kk++) {
            float4 v4 = *(const float4*)&kv_s[kk * 68 + tk * 4];
            const float wa = wr0[kk], wb = wr1[kk];
            a0.x += wa * v4.x; a0.y += wa * v4.y; a0.z += wa * v4.z; a0.w += wa * v4.w;
            a1.x += wb * v4.x; a1.y += wb * v4.y; a1.z += wb * v4.z; a1.w += wb * v4.w;
        }
    }

    float* optr = Attn + ((long long)(b * 128 + q0 + tq * 2)) * 512 + h * 64 + tk * 4;
    *(float4*)optr = a0;
    *(float4*)(optr + 512) = a1;
}

// ---------------------------------------------------------------------------
extern "C" void kernel_launch(void* const* d_in, const int* in_sizes, int n_in,
                              void* d_out, int out_size)
{
    const float* entities  = (const float*)d_in[0];
    const int*   pre_mask  = (const int*)d_in[1];
    const float* diff_mask = (const float*)d_in[2];
    const int*   post_mask = (const int*)d_in[3];
    const float* W_in      = (const float*)d_in[4];
    const float* W_out     = (const float*)d_in[5];
    const float* b_out     = (const float*)d_in[6];
    float*       out       = (float*)d_out;

    float *q_buf, *kv_buf, *attn_buf;
    cudaGetSymbolAddress((void**)&q_buf, g_q);
    cudaGetSymbolAddress((void**)&kv_buf, g_kv);
    cudaGetSymbolAddress((void**)&attn_buf, g_attn);

    cudaFuncSetAttribute(attn_kernel, cudaFuncAttributeMaxDynamicSharedMemorySize,
                         ATTN_SMEM_BYTES);

    // Q = entities[:, :128, :] @ W_in[0:512]^T     (M=16384, N=512, K=512)
    sgemm_nt<<<dim3(4, 128), 256>>>(entities, W_in, q_buf,
                                    16384, 512, 512, 128, 512LL * 512, nullptr, nullptr);
    // KV = entities @ W_in[512:1536]^T             (M=65536, N=1024, K=512)
    sgemm_nt<<<dim3(8, 512), 256>>>(entities, W_in + 512 * 512, kv_buf,
                                    65536, 1024, 512, 0, 0, nullptr, nullptr);
    // attention
    attn_kernel<<<dim3(4, 8, 128), 256, ATTN_SMEM_BYTES>>>(
        q_buf, kv_buf, pre_mask, diff_mask, attn_buf);
    // out = attn @ W_out^T + b_out, rows zeroed by post_mask  (M=16384, N=512, K=512)
    sgemm_nt<<<dim3(4, 128), 256>>>(attn_buf, W_out, out,
                                    16384, 512, 512, 0, 0, b_out, post_mask);
}

// round 8
// speedup vs baseline: 1.8209x; 1.8209x over previous
#include <cuda_runtime.h>
#include <cuda_bf16.h>
#include <math.h>
#include <stdint.h>

// BS=128, NE=512, NQ=128, E=512, H=8, HD=64. Masks int32.
// tcgen05 unavailable (harness emits .target sm_103 PTX) -> mma.sync HMMA path.

// ---------------- scratch ----------------
__device__ __nv_bfloat16 g_entX[67108864];   // 65536 x 1024 [hi|lo]
__device__ __nv_bfloat16 g_wX[1572864];      // 1536 x 1024  [hi|lo] (Wq 0-511, Wkv 512-1535)
__device__ __nv_bfloat16 g_woX[524288];      // 512 x 1024   [hi|lo]
__device__ __nv_bfloat16 g_attnX[16777216];  // 16384 x 1024 [hi|lo]
__device__ float g_q[8388608];               // 16384 x 512
__device__ float g_kv[67108864];             // 65536 x 1024 (K | V)
__device__ float g_attn[8388608];            // 16384 x 512

// ---------------- helpers ----------------
__device__ __forceinline__ uint32_t smem_u32(const void* p) {
    uint32_t a;
    asm("{ .reg .u64 t; cvta.to.shared.u64 t, %1; cvt.u32.u64 %0, t; }" : "=r"(a) : "l"(p));
    return a;
}
#define CP16(dst, src)  asm volatile("cp.async.cg.shared.global [%0], [%1], 16;" :: "r"(dst), "l"(src))
#define CPCOMMIT()      asm volatile("cp.async.commit_group;" ::: "memory")
#define CPWAIT1()       asm volatile("cp.async.wait_group 1;" ::: "memory")
#define CPWAIT0()       asm volatile("cp.async.wait_group 0;" ::: "memory")

__device__ __forceinline__ void ldsm4(uint32_t& r0, uint32_t& r1, uint32_t& r2, uint32_t& r3,
                                      uint32_t addr) {
    asm volatile("ldmatrix.sync.aligned.m8n8.x4.shared.b16 {%0,%1,%2,%3}, [%4];"
                 : "=r"(r0), "=r"(r1), "=r"(r2), "=r"(r3) : "r"(addr));
}
__device__ __forceinline__ void mma16816(float* d, uint32_t a0, uint32_t a1, uint32_t a2,
                                         uint32_t a3, uint32_t b0, uint32_t b1) {
    asm volatile(
        "mma.sync.aligned.m16n8k16.row.col.f32.bf16.bf16.f32 "
        "{%0,%1,%2,%3}, {%4,%5,%6,%7}, {%8,%9}, {%0,%1,%2,%3};"
        : "+f"(d[0]), "+f"(d[1]), "+f"(d[2]), "+f"(d[3])
        : "r"(a0), "r"(a1), "r"(a2), "r"(a3), "r"(b0), "r"(b1));
}

// ---------------- expand: fp32 -> [hi|lo] bf16 (rows of 512) ----------------
__global__ void __launch_bounds__(256) expand_hilo(
    const float* __restrict__ src, __nv_bfloat16* __restrict__ dst, long long n4)
{
    long long i = (long long)blockIdx.x * 256 + threadIdx.x;
    if (i >= n4) return;
    long long row = i >> 7;
    int k4 = (int)(i & 127);
    float4 v = ((const float4*)src)[i];
    __nv_bfloat16 h[4], l[4];
    h[0] = __float2bfloat16(v.x); l[0] = __float2bfloat16(v.x - __bfloat162float(h[0]));
    h[1] = __float2bfloat16(v.y); l[1] = __float2bfloat16(v.y - __bfloat162float(h[1]));
    h[2] = __float2bfloat16(v.z); l[2] = __float2bfloat16(v.z - __bfloat162float(h[2]));
    h[3] = __float2bfloat16(v.w); l[3] = __float2bfloat16(v.w - __bfloat162float(h[3]));
    *(uint2*)(dst + row * 1024 + k4 * 4)       = *(uint2*)h;
    *(uint2*)(dst + row * 1024 + 512 + k4 * 4) = *(uint2*)l;
}

// ---------------- HMMA bf16 GEMM (NT, hi/lo 3-term) ----------------
// C[m,n] = sum over K'=1536: chunks 0-7 Ah.Bh, 8-15 Ah.Bl, 16-23 Al.Bh.
// 128x128 tile, 8 warps (4 M x 2 N), warp = 32x64 via m16n8k16.
// smem per buffer: A 128x(64+8pad) bf16 = 18432 B, B same. Double buffered: 73728 B.
#define NCHUNK 24
#define ROWB 144                 // row stride bytes (72 bf16)
#define BUFB 36864               // one (A+B) buffer
#define GEMM_SMEM (2 * BUFB)

__global__ void __launch_bounds__(256) gemm_hmma(
    const __nv_bfloat16* __restrict__ A, const __nv_bfloat16* __restrict__ B,
    float* __restrict__ C, int N_total, int remap,
    const float* __restrict__ bias, const int* __restrict__ pmask)
{
    extern __shared__ char smem[];
    const uint32_t sb = smem_u32(smem);
    const int tid = threadIdx.x;
    const int wid = tid >> 5, lane = tid & 31;
    const int wm = wid & 3;            // 0..3 (M)
    const int wn = wid >> 2;           // 0..1 (N)
    const int m0 = blockIdx.y * 128;
    const int n0 = blockIdx.x * 128;

    // global load map: 4 vec16 for A + 4 for B per thread per chunk
    const __nv_bfloat16* srcA[4];
    const __nv_bfloat16* srcB[4];
    uint32_t dstA[4], dstB[4];
    #pragma unroll
    for (int j = 0; j < 4; j++) {
        const int lin = tid + j * 256;
        const int row = lin >> 3, seg = lin & 7;
        const long long am = m0 + row;
        const long long ar = remap ? (am >> 7) * 512 + (am & 127) : am;
        srcA[j] = A + ar * 1024 + seg * 8;
        srcB[j] = B + (long long)(n0 + row) * 1024 + seg * 8;
        dstA[j] = (uint32_t)(row * ROWB + seg * 16);
        dstB[j] = (uint32_t)(18432 + row * ROWB + seg * 16);
    }

    // ldmatrix lane-address offsets (within a buffer), + ks*32 bytes per k16 step
    const int aRow = wm * 32 + (lane & 15);
    uint32_t aOff[2];
    #pragma unroll
    for (int mf = 0; mf < 2; mf++)
        aOff[mf] = (uint32_t)((aRow + mf * 16) * ROWB + ((lane >> 4) << 4));
    const int bRow = wn * 64 + (lane & 7) + ((lane >> 4) << 3);
    uint32_t bOff[4];
    #pragma unroll
    for (int nf = 0; nf < 4; nf++)
        bOff[nf] = (uint32_t)(18432 + (bRow + nf * 16) * ROWB + (((lane >> 3) & 1) << 4));

    float acc[2][8][4];
    #pragma unroll
    for (int i = 0; i < 2; i++)
        #pragma unroll
        for (int j = 0; j < 8; j++)
            #pragma unroll
            for (int k = 0; k < 4; k++) acc[i][j][k] = 0.f;

    // prologue: chunks 0,1
    #pragma unroll
    for (int c = 0; c < 2; c++) {
        const int ca = (c < 8 ? c : c - 8) * 64;
        const int cb = (c < 16 ? c : c - 16) * 64;
        const uint32_t base = sb + c * BUFB;
        #pragma unroll
        for (int j = 0; j < 4; j++) {
            CP16(base + dstA[j], srcA[j] + ca);
            CP16(base + dstB[j], srcB[j] + cb);
        }
        CPCOMMIT();
    }

    #pragma unroll 1
    for (int c = 0; c < NCHUNK; c++) {
        if (c < NCHUNK - 1) CPWAIT1(); else CPWAIT0();
        __syncthreads();

        const uint32_t base = sb + (c & 1) * BUFB;
        #pragma unroll
        for (int ks = 0; ks < 4; ks++) {
            uint32_t a[2][4], b[4][4];
            #pragma unroll
            for (int mf = 0; mf < 2; mf++)
                ldsm4(a[mf][0], a[mf][1], a[mf][2], a[mf][3], base + aOff[mf] + ks * 32);
            #pragma unroll
            for (int nf = 0; nf < 4; nf++)
                ldsm4(b[nf][0], b[nf][1], b[nf][2], b[nf][3], base + bOff[nf] + ks * 32);
            #pragma unroll
            for (int mf = 0; mf < 2; mf++)
                #pragma unroll
                for (int nf = 0; nf < 4; nf++) {
                    mma16816(acc[mf][nf * 2 + 0], a[mf][0], a[mf][1], a[mf][2], a[mf][3],
                             b[nf][0], b[nf][1]);
                    mma16816(acc[mf][nf * 2 + 1], a[mf][0], a[mf][1], a[mf][2], a[mf][3],
                             b[nf][2], b[nf][3]);
                }
        }

        if (c + 2 < NCHUNK) {
            __syncthreads();   // all warps done reading buf (c&1) before overwrite
            const int cn = c + 2;
            const int ca = (cn < 8 ? cn : cn - 8) * 64;
            const int cb = (cn < 16 ? cn : cn - 16) * 64;
            const uint32_t nb = sb + (cn & 1) * BUFB;
            #pragma unroll
            for (int j = 0; j < 4; j++) {
                CP16(nb + dstA[j], srcA[j] + ca);
                CP16(nb + dstB[j], srcB[j] + cb);
            }
            CPCOMMIT();
        }
    }

    // epilogue: frag layout -> C, with optional bias / row zero-mask
    const int mrow = m0 + wm * 32 + (lane >> 2);
    const int ncol = n0 + wn * 64 + 2 * (lane & 3);
    #pragma unroll
    for (int mf = 0; mf < 2; mf++) {
        #pragma unroll
        for (int half = 0; half < 2; half++) {
            const int m = mrow + mf * 16 + half * 8;
            const bool zr = (pmask != nullptr) && (pmask[m] != 0);
            float* crow = C + (long long)m * N_total;
            #pragma unroll
            for (int nf = 0; nf < 8; nf++) {
                const int n = ncol + nf * 8;
                float2 o;
                if (zr) {
                    o.x = 0.f; o.y = 0.f;
                } else {
                    o.x = acc[mf][nf][half * 2 + 0];
                    o.y = acc[mf][nf][half * 2 + 1];
                    if (bias) { o.x += bias[n]; o.y += bias[n + 1]; }
                }
                *(float2*)(crow + n) = o;
            }
        }
    }
}

// ---------------- fused attention (unchanged, passing fp32 path) ----------------
#define ATTN_SMEM_BYTES ((32 * 68 + 64 * 68 + 32 * 512) * 4)

__global__ void __launch_bounds__(256) attn_kernel(
    const float* __restrict__ Q, const float* __restrict__ KV,
    const int* __restrict__ pre_mask,
    const float* __restrict__ diff_mask,
    float* __restrict__ Attn)
{
    extern __shared__ float sm[];
    float* q_s  = sm;
    float* kv_s = sm + 32 * 68;
    float* w_s  = sm + 32 * 68 + 64 * 68;

    const int tid = threadIdx.x;
    const int q0 = blockIdx.x * 32;
    const int h  = blockIdx.y;
    const int b  = blockIdx.z;

    const float* qptr  = Q + ((long long)(b * 128 + q0)) * 512 + h * 64;
    const float* kbase = KV + (long long)b * 512 * 1024 + h * 64;
    const float* vbase = kbase + 512;

    #pragma unroll
    for (int i = 0; i < 2; i++) {
        const int lin = tid + i * 256;
        const int r = lin >> 4, c = (lin & 15) * 4;
        *(float4*)&q_s[r * 68 + c] = *(const float4*)(qptr + (long long)r * 512 + c);
    }

    const int tk = tid & 15;
    const int tq = tid >> 4;

    for (int kt = 0; kt < 8; kt++) {
        __syncthreads();
        #pragma unroll
        for (int i = 0; i < 4; i++) {
            const int lin = tid + i * 256;
            const int key = lin >> 4, c = (lin & 15) * 4;
            float4 v = *(const float4*)(kbase + (long long)(kt * 64 + key) * 1024 + c);
            kv_s[(c + 0) * 68 + key] = v.x;
            kv_s[(c + 1) * 68 + key] = v.y;
            kv_s[(c + 2) * 68 + key] = v.z;
            kv_s[(c + 3) * 68 + key] = v.w;
        }
        __syncthreads();

        float4 l0 = make_float4(0.f, 0.f, 0.f, 0.f);
        float4 l1 = make_float4(0.f, 0.f, 0.f, 0.f);
        const float* qr0 = &q_s[(tq * 2 + 0) * 68];
        const float* qr1 = &q_s[(tq * 2 + 1) * 68];
        #pragma unroll 8
        for (int d = 0; d < 64; d++) {
            float4 k4 = *(const float4*)&kv_s[d * 68 + tk * 4];
            const float qa = qr0[d], qb = qr1[d];
            l0.x += qa * k4.x; l0.y += qa * k4.y; l0.z += qa * k4.z; l0.w += qa * k4.w;
            l1.x += qb * k4.x; l1.y += qb * k4.y; l1.z += qb * k4.z; l1.w += qb * k4.w;
        }

        #pragma unroll
        for (int r = 0; r < 2; r++) {
            const int qi = tq * 2 + r;
            const float4 lv = r ? l1 : l0;
            const int4 m4 = *(const int4*)(pre_mask +
                ((long long)(b * 128 + q0 + qi)) * 512 + kt * 64 + tk * 4);
            float4 o;
            o.x = m4.x ? -INFINITY : lv.x * 0.125f;
            o.y = m4.y ? -INFINITY : lv.y * 0.125f;
            o.z = m4.z ? -INFINITY : lv.z * 0.125f;
            o.w = m4.w ? -INFINITY : lv.w * 0.125f;
            *(float4*)&w_s[qi * 512 + kt * 64 + tk * 4] = o;
        }
    }
    __syncthreads();

    const int warp = tid >> 5, lane = tid & 31;
    for (int rr = 0; rr < 4; rr++) {
        const int r = warp * 4 + rr;
        float vals[16];
        float mx = -INFINITY;
        #pragma unroll
        for (int i = 0; i < 16; i++) {
            vals[i] = w_s[r * 512 + lane + 32 * i];
            mx = fmaxf(mx, vals[i]);
        }
        #pragma unroll
        for (int o = 16; o > 0; o >>= 1) mx = fmaxf(mx, __shfl_xor_sync(0xffffffffu, mx, o));

        if (mx == -INFINITY) {
            #pragma unroll
            for (int i = 0; i < 16; i++) w_s[r * 512 + lane + 32 * i] = 0.f;
            continue;
        }
        float s1 = 0.f;
        #pragma unroll
        for (int i = 0; i < 16; i++) { vals[i] = __expf(vals[i] - mx); s1 += vals[i]; }
        #pragma unroll
        for (int o = 16; o > 0; o >>= 1) s1 += __shfl_xor_sync(0xffffffffu, s1, o);

        const float* drow = diff_mask + ((long long)(b * 128 + q0 + r)) * 512;
        float s2 = 0.f;
        #pragma unroll
        for (int i = 0; i < 16; i++) { vals[i] *= drow[lane + 32 * i]; s2 += vals[i]; }
        #pragma unroll
        for (int o = 16; o > 0; o >>= 1) s2 += __shfl_xor_sync(0xffffffffu, s2, o);

        const float inv = 1.f / (s2 + 1e-8f * s1);
        #pragma unroll
        for (int i = 0; i < 16; i++) w_s[r * 512 + lane + 32 * i] = vals[i] * inv;
    }

    float4 a0 = make_float4(0.f, 0.f, 0.f, 0.f);
    float4 a1 = make_float4(0.f, 0.f, 0.f, 0.f);
    for (int vt = 0; vt < 8; vt++) {
        __syncthreads();
        #pragma unroll
        for (int i = 0; i < 4; i++) {
            const int lin = tid + i * 256;
            const int key = lin >> 4, c = (lin & 15) * 4;
            *(float4*)&kv_s[key * 68 + c] =
                *(const float4*)(vbase + (long long)(vt * 64 + key) * 1024 + c);
        }
        __syncthreads();

        const float* wr0 = &w_s[(tq * 2 + 0) * 512 + vt * 64];
        const float* wr1 = &w_s[(tq * 2 + 1) * 512 + vt * 64];
        #pragma unroll 8
        for (int kk = 0; kk < 64; kk++) {
            float4 v4 = *(const float4*)&kv_s[kk * 68 + tk * 4];
            const float wa = wr0[kk], wb = wr1[kk];
            a0.x += wa * v4.x; a0.y += wa * v4.y; a0.z += wa * v4.z; a0.w += wa * v4.w;
            a1.x += wb * v4.x; a1.y += wb * v4.y; a1.z += wb * v4.z; a1.w += wb * v4.w;
        }
    }

    float* optr = Attn + ((long long)(b * 128 + q0 + tq * 2)) * 512 + h * 64 + tk * 4;
    *(float4*)optr = a0;
    *(float4*)(optr + 512) = a1;
}

// ---------------------------------------------------------------------------
extern "C" void kernel_launch(void* const* d_in, const int* in_sizes, int n_in,
                              void* d_out, int out_size)
{
    const float* entities  = (const float*)d_in[0];
    const int*   pre_mask  = (const int*)d_in[1];
    const float* diff_mask = (const float*)d_in[2];
    const int*   post_mask = (const int*)d_in[3];
    const float* W_in      = (const float*)d_in[4];
    const float* W_out     = (const float*)d_in[5];
    const float* b_out     = (const float*)d_in[6];
    float*       out       = (float*)d_out;

    __nv_bfloat16 *entX, *wX, *woX, *attnX;
    float *q_buf, *kv_buf, *attn_buf;
    cudaGetSymbolAddress((void**)&entX, g_entX);
    cudaGetSymbolAddress((void**)&wX, g_wX);
    cudaGetSymbolAddress((void**)&woX, g_woX);
    cudaGetSymbolAddress((void**)&attnX, g_attnX);
    cudaGetSymbolAddress((void**)&q_buf, g_q);
    cudaGetSymbolAddress((void**)&kv_buf, g_kv);
    cudaGetSymbolAddress((void**)&attn_buf, g_attn);

    cudaFuncSetAttribute(gemm_hmma, cudaFuncAttributeMaxDynamicSharedMemorySize, GEMM_SMEM);
    cudaFuncSetAttribute(attn_kernel, cudaFuncAttributeMaxDynamicSharedMemorySize,
                         ATTN_SMEM_BYTES);

    // hi/lo expansions
    expand_hilo<<<(65536LL * 128 + 255) / 256, 256>>>(entities, entX, 65536LL * 128);
    expand_hilo<<<(1536LL * 128 + 255) / 256, 256>>>(W_in, wX, 1536LL * 128);
    expand_hilo<<<(512LL * 128 + 255) / 256, 256>>>(W_out, woX, 512LL * 128);

    // Q = ent[:, :128] @ Wq^T       (16384 x 512)
    gemm_hmma<<<dim3(4, 128), 256, GEMM_SMEM>>>(entX, wX, q_buf, 512, 1, nullptr, nullptr);
    // KV = ent @ Wkv^T              (65536 x 1024)
    gemm_hmma<<<dim3(8, 512), 256, GEMM_SMEM>>>(entX, wX + 512 * 1024, kv_buf, 1024, 0,
                                                nullptr, nullptr);
    // attention
    attn_kernel<<<dim3(4, 8, 128), 256, ATTN_SMEM_BYTES>>>(
        q_buf, kv_buf, pre_mask, diff_mask, attn_buf);
    // out = attn @ W_out^T + b_out, post-masked
    expand_hilo<<<(16384LL * 128 + 255) / 256, 256>>>(attn_buf, attnX, 16384LL * 128);
    gemm_hmma<<<dim3(4, 128), 256, GEMM_SMEM>>>(attnX, woX, out, 512, 0, b_out, post_mask);
}